// round 1
// baseline (speedup 1.0000x reference)
#include <cuda_runtime.h>

// GlobalAggregator: B=128, N=512, K=12, DIM=128
// out[b,n,:] = relu( concat(self, sum_k softmax_k(score) * neigh) @ w3 )
// score[k] = lrelu( (extra*neigh[k] ++ weight[k]) @ w1 ) @ w2

#define BB 128
#define NN 512
#define KK 12
#define DIMD 128
#define FF 129  // DIM+1

__device__ __forceinline__ unsigned long long dup2(float x) {
    unsigned long long r;
    asm("mov.b64 %0, {%1, %1};" : "=l"(r) : "f"(x));
    return r;
}
__device__ __forceinline__ void fma2(unsigned long long& acc, unsigned long long a, unsigned long long b) {
    asm("fma.rn.f32x2 %0, %1, %2, %0;" : "+l"(acc) : "l"(a), "l"(b));
}

__global__ __launch_bounds__(128) void gat_fused_kernel(
    const float* __restrict__ self_v,   // [B,N,DIM]
    const float* __restrict__ neigh,    // [B,N,K,DIM]
    const float* __restrict__ nw,       // [B,N,K]
    const float* __restrict__ extra,    // [B,N,DIM]
    const float* __restrict__ w1,       // [129,128]
    const float* __restrict__ w2,       // [128,1]
    const float* __restrict__ w3,       // [256,128]
    float* __restrict__ out)            // [B,N,DIM]
{
    __shared__ __align__(16) float feat_s[FF * KK];   // [f][k], 48B rows
    __shared__ float cat_s[2 * DIMD];
    __shared__ float red_s[KK * 4];
    __shared__ float alpha_s[KK];

    const int bn = blockIdx.x;
    const int d = threadIdx.x;              // 0..127
    const float* nb = neigh + (size_t)bn * KK * DIMD;

    // ---- Phase A: stage feat[f][k] = extra[f]*neigh[k][f]; feat[128][k] = weight[k]
    float exf = extra[(size_t)bn * DIMD + d];
#pragma unroll
    for (int k = 0; k < KK; k++)
        feat_s[d * KK + k] = exf * __ldcs(nb + k * DIMD + d);
    if (d < KK)
        feat_s[DIMD * KK + d] = nw[(size_t)bn * KK + d];
    __syncthreads();

    // ---- Phase B: alpha_pre[k][d] = sum_f feat[f][k] * w1[f][d]  (packed f32x2, k-pairs)
    unsigned long long acc[6];
#pragma unroll
    for (int j = 0; j < 6; j++) acc[j] = 0ULL;
    const float* w1c = w1 + d;
#pragma unroll 3
    for (int f = 0; f < FF; f++) {
        unsigned long long w = dup2(w1c[f * DIMD]);
        const ulonglong2* row = (const ulonglong2*)(feat_s + f * KK);
        ulonglong2 p0 = row[0];
        ulonglong2 p1 = row[1];
        ulonglong2 p2 = row[2];
        fma2(acc[0], p0.x, w);
        fma2(acc[1], p0.y, w);
        fma2(acc[2], p1.x, w);
        fma2(acc[3], p1.y, w);
        fma2(acc[4], p2.x, w);
        fma2(acc[5], p2.y, w);
    }

    // ---- Phase C: leaky_relu, dot with w2 (reduce over d), softmax over k
    float w2d = w2[d];
    float sc[KK];
#pragma unroll
    for (int j = 0; j < 6; j++) {
        float lo = __uint_as_float((unsigned)(acc[j] & 0xffffffffULL));
        float hi = __uint_as_float((unsigned)(acc[j] >> 32));
        lo = lo > 0.f ? lo : 0.2f * lo;
        hi = hi > 0.f ? hi : 0.2f * hi;
        sc[2 * j]     = lo * w2d;
        sc[2 * j + 1] = hi * w2d;
    }
#pragma unroll
    for (int k = 0; k < KK; k++) {
        float v = sc[k];
        v += __shfl_xor_sync(0xffffffffu, v, 16);
        v += __shfl_xor_sync(0xffffffffu, v, 8);
        v += __shfl_xor_sync(0xffffffffu, v, 4);
        v += __shfl_xor_sync(0xffffffffu, v, 2);
        v += __shfl_xor_sync(0xffffffffu, v, 1);
        if ((d & 31) == 0) red_s[k * 4 + (d >> 5)] = v;
    }
    __syncthreads();
    if (d == 0) {
        float s[KK];
        float m = -1e30f;
#pragma unroll
        for (int k = 0; k < KK; k++) {
            s[k] = red_s[k * 4] + red_s[k * 4 + 1] + red_s[k * 4 + 2] + red_s[k * 4 + 3];
            m = fmaxf(m, s[k]);
        }
        float tot = 0.f;
#pragma unroll
        for (int k = 0; k < KK; k++) {
            s[k] = __expf(s[k] - m);
            tot += s[k];
        }
        float inv = 1.f / tot;
#pragma unroll
        for (int k = 0; k < KK; k++) alpha_s[k] = s[k] * inv;
    }
    __syncthreads();

    // ---- Phase D: agg[d] = sum_k alpha[k] * neigh[k][d];  build concat in smem
    float agg = 0.f;
#pragma unroll
    for (int k = 0; k < KK; k++)
        agg = fmaf(alpha_s[k], __ldcs(nb + k * DIMD + d), agg);
    cat_s[d] = self_v[(size_t)bn * DIMD + d];
    cat_s[DIMD + d] = agg;
    __syncthreads();

    // ---- Phase E: out[d] = relu( sum_f cat[f] * w3[f][d] )
    float o = 0.f;
    const float* w3c = w3 + d;
#pragma unroll 8
    for (int f = 0; f < 2 * DIMD; f++)
        o = fmaf(cat_s[f], w3c[f * DIMD], o);
    out[(size_t)bn * DIMD + d] = fmaxf(o, 0.f);
}

extern "C" void kernel_launch(void* const* d_in, const int* in_sizes, int n_in,
                              void* d_out, int out_size) {
    // metadata order: self_vectors, neighbor_vector, neighbor_weight, extra_vector,
    //                 masks (unused), batch_size (unused), w_1, w_2, w_3
    const float* self_v = (const float*)d_in[0];
    const float* neigh  = (const float*)d_in[1];
    const float* nw     = (const float*)d_in[2];
    const float* extra  = (const float*)d_in[3];
    const float* w1     = (const float*)d_in[6];
    const float* w2     = (const float*)d_in[7];
    const float* w3     = (const float*)d_in[8];
    float* out = (float*)d_out;

    gat_fused_kernel<<<BB * NN, 128>>>(self_v, neigh, nw, extra, w1, w2, w3, out);
}

// round 2
// speedup vs baseline: 1.6058x; 1.6058x over previous
#include <cuda_runtime.h>

// GlobalAggregator: B=128, N=512, K=12, DIM=128
// Warp-per-(b,n): lane owns output columns 4*lane..4*lane+3.

#define KK 12
#define DIMD 128
#define FF 129           // DIM+1
#define ROWS 16          // feat row stride in floats (64B, swizzled quads)

__device__ __forceinline__ unsigned long long dup2(float x) {
    unsigned long long r;
    asm("mov.b64 %0, {%1, %1};" : "=l"(r) : "f"(x));
    return r;
}
__device__ __forceinline__ void fma2(unsigned long long& acc, unsigned long long a, unsigned long long b) {
    asm("fma.rn.f32x2 %0, %1, %2, %0;" : "+l"(acc) : "l"(a), "l"(b));
}
__device__ __forceinline__ float lo32(unsigned long long v) {
    return __uint_as_float((unsigned)(v & 0xffffffffULL));
}
__device__ __forceinline__ float hi32(unsigned long long v) {
    return __uint_as_float((unsigned)(v >> 32));
}
__device__ __forceinline__ float lrelu(float x) {
    return fmaxf(x, 0.f) + 0.2f * fminf(x, 0.f);
}

__global__ __launch_bounds__(128) void gat_warp_kernel(
    const float* __restrict__ self_v,   // [B,N,DIM]
    const float* __restrict__ neigh,    // [B,N,K,DIM]
    const float* __restrict__ nw,       // [B,N,K]
    const float* __restrict__ extra,    // [B,N,DIM]
    const float* __restrict__ w1,       // [129,128]
    const float* __restrict__ w2,       // [128]
    const float* __restrict__ w3,       // [256,128]
    float* __restrict__ out)            // [B,N,DIM]
{
    __shared__ __align__(16) float feat_sh[4][(FF + 1) * ROWS]; // per-warp 8320B
    __shared__ __align__(16) float cat_sh[4][2 * DIMD];

    const int warp = threadIdx.x >> 5;
    const int lane = threadIdx.x & 31;
    const int bn = blockIdx.x * 4 + warp;

    float* feat_s = feat_sh[warp];
    float* cat_s  = cat_sh[warp];

    const float4* nb4 = (const float4*)(neigh + (size_t)bn * KK * DIMD);

    // ---- Phase A: feat rows f = 4*lane..4*lane+3 (k = 0..11 each), swizzled quads
    {
        float4 ex = *(const float4*)(extra + (size_t)bn * DIMD + 4 * lane);
        float rows[4][KK];
#pragma unroll
        for (int k = 0; k < KK; k++) {
            float4 v = nb4[k * 32 + lane];
            rows[0][k] = ex.x * v.x;
            rows[1][k] = ex.y * v.y;
            rows[2][k] = ex.z * v.z;
            rows[3][k] = ex.w * v.w;
        }
#pragma unroll
        for (int j = 0; j < 4; j++) {
            int f = 4 * lane + j;
#pragma unroll
            for (int c = 0; c < 3; c++) {
                int cp = (c + lane) & 3;   // swizzle key = f>>2 = lane
                *(float4*)&feat_s[f * ROWS + 4 * cp] =
                    make_float4(rows[j][4 * c], rows[j][4 * c + 1],
                                rows[j][4 * c + 2], rows[j][4 * c + 3]);
            }
        }
        if (lane < KK)  // row f=128: swizzle key (128>>2)&3 == 0 -> identity
            feat_s[DIMD * ROWS + lane] = nw[(size_t)bn * KK + lane];
    }
    __syncwarp();

    // ---- Phase B: alpha_pre[k][d] = sum_f feat[f][k] * w1[f][d], d = 4*lane+j
    unsigned long long acc[4][6];
#pragma unroll
    for (int j = 0; j < 4; j++)
#pragma unroll
        for (int p = 0; p < 6; p++) acc[j][p] = 0ULL;

    const float4* w1r = (const float4*)w1 + lane;   // w1[f][4*lane..]
#pragma unroll 2
    for (int f = 0; f < FF; f++) {
        float4 wv = w1r[f * 32];
        int g = (f >> 2) & 3;
        const float* row = feat_s + f * ROWS;
        ulonglong2 qa = *(const ulonglong2*)(row + 4 * ((0 + g) & 3)); // k0..3
        ulonglong2 qb = *(const ulonglong2*)(row + 4 * ((1 + g) & 3)); // k4..7
        ulonglong2 qc = *(const ulonglong2*)(row + 4 * ((2 + g) & 3)); // k8..11
        unsigned long long w0 = dup2(wv.x), w1d = dup2(wv.y),
                           w2d = dup2(wv.z), w3d = dup2(wv.w);
        fma2(acc[0][0], qa.x, w0); fma2(acc[0][1], qa.y, w0);
        fma2(acc[0][2], qb.x, w0); fma2(acc[0][3], qb.y, w0);
        fma2(acc[0][4], qc.x, w0); fma2(acc[0][5], qc.y, w0);
        fma2(acc[1][0], qa.x, w1d); fma2(acc[1][1], qa.y, w1d);
        fma2(acc[1][2], qb.x, w1d); fma2(acc[1][3], qb.y, w1d);
        fma2(acc[1][4], qc.x, w1d); fma2(acc[1][5], qc.y, w1d);
        fma2(acc[2][0], qa.x, w2d); fma2(acc[2][1], qa.y, w2d);
        fma2(acc[2][2], qb.x, w2d); fma2(acc[2][3], qb.y, w2d);
        fma2(acc[2][4], qc.x, w2d); fma2(acc[2][5], qc.y, w2d);
        fma2(acc[3][0], qa.x, w3d); fma2(acc[3][1], qa.y, w3d);
        fma2(acc[3][2], qb.x, w3d); fma2(acc[3][3], qb.y, w3d);
        fma2(acc[3][4], qc.x, w3d); fma2(acc[3][5], qc.y, w3d);
    }

    // ---- Phase C: leaky_relu, dot w2 (reduce over d), softmax over k (per-lane)
    float s[KK];
    {
        float4 w2v = *(const float4*)(w2 + 4 * lane);
        float wj[4] = {w2v.x, w2v.y, w2v.z, w2v.w};
#pragma unroll
        for (int p = 0; p < 6; p++) {
            float slo = 0.f, shi = 0.f;
#pragma unroll
            for (int j = 0; j < 4; j++) {
                slo += lrelu(lo32(acc[j][p])) * wj[j];
                shi += lrelu(hi32(acc[j][p])) * wj[j];
            }
            s[2 * p] = slo;
            s[2 * p + 1] = shi;
        }
    }
#pragma unroll
    for (int k = 0; k < KK; k++) {
#pragma unroll
        for (int off = 16; off > 0; off >>= 1)
            s[k] += __shfl_xor_sync(0xffffffffu, s[k], off);
    }
    float alpha[KK];
    {
        float m = s[0];
#pragma unroll
        for (int k = 1; k < KK; k++) m = fmaxf(m, s[k]);
        float tot = 0.f;
#pragma unroll
        for (int k = 0; k < KK; k++) {
            alpha[k] = __expf(s[k] - m);
            tot += alpha[k];
        }
        float inv = 1.f / tot;
#pragma unroll
        for (int k = 0; k < KK; k++) alpha[k] *= inv;
    }

    // ---- Phase D: agg[4] = sum_k alpha[k] * neigh[k][4*lane+j]; build concat
    {
        float4 agg = make_float4(0.f, 0.f, 0.f, 0.f);
#pragma unroll
        for (int k = 0; k < KK; k++) {
            float4 v = nb4[k * 32 + lane];   // L1 hit (loaded in Phase A)
            agg.x = fmaf(alpha[k], v.x, agg.x);
            agg.y = fmaf(alpha[k], v.y, agg.y);
            agg.z = fmaf(alpha[k], v.z, agg.z);
            agg.w = fmaf(alpha[k], v.w, agg.w);
        }
        float4 sv = *(const float4*)(self_v + (size_t)bn * DIMD + 4 * lane);
        *(float4*)&cat_s[4 * lane] = sv;
        *(float4*)&cat_s[DIMD + 4 * lane] = agg;
    }
    __syncwarp();

    // ---- Phase E: out[d] = relu( sum_f cat[f] * w3[f][d] )
    {
        unsigned long long eacc[8];
#pragma unroll
        for (int t = 0; t < 8; t++) eacc[t] = 0ULL;
        const float4* w3r = (const float4*)w3 + lane;
#pragma unroll 4
        for (int f0 = 0; f0 < 2 * DIMD; f0 += 4) {
            float4 cv = *(const float4*)&cat_s[f0];   // broadcast
            float cvj[4] = {cv.x, cv.y, cv.z, cv.w};
#pragma unroll
            for (int t = 0; t < 4; t++) {
                float4 w3v = w3r[(f0 + t) * 32];
                unsigned long long cd = dup2(cvj[t]);
                unsigned long long wl, wh;
                asm("mov.b64 %0, {%1, %2};" : "=l"(wl) : "f"(w3v.x), "f"(w3v.y));
                asm("mov.b64 %0, {%1, %2};" : "=l"(wh) : "f"(w3v.z), "f"(w3v.w));
                fma2(eacc[2 * t], wl, cd);
                fma2(eacc[2 * t + 1], wh, cd);
            }
        }
        float o0 = lo32(eacc[0]) + lo32(eacc[2]) + lo32(eacc[4]) + lo32(eacc[6]);
        float o1 = hi32(eacc[0]) + hi32(eacc[2]) + hi32(eacc[4]) + hi32(eacc[6]);
        float o2 = lo32(eacc[1]) + lo32(eacc[3]) + lo32(eacc[5]) + lo32(eacc[7]);
        float o3 = hi32(eacc[1]) + hi32(eacc[3]) + hi32(eacc[5]) + hi32(eacc[7]);
        float4 o = make_float4(fmaxf(o0, 0.f), fmaxf(o1, 0.f),
                               fmaxf(o2, 0.f), fmaxf(o3, 0.f));
        *(float4*)(out + (size_t)bn * DIMD + 4 * lane) = o;
    }
}

extern "C" void kernel_launch(void* const* d_in, const int* in_sizes, int n_in,
                              void* d_out, int out_size) {
    const float* self_v = (const float*)d_in[0];
    const float* neigh  = (const float*)d_in[1];
    const float* nw     = (const float*)d_in[2];
    const float* extra  = (const float*)d_in[3];
    const float* w1     = (const float*)d_in[6];
    const float* w2     = (const float*)d_in[7];
    const float* w3     = (const float*)d_in[8];
    float* out = (float*)d_out;

    gat_warp_kernel<<<(128 * 512) / 4, 128>>>(self_v, neigh, nw, extra, w1, w2, w3, out);
}

// round 3
// speedup vs baseline: 1.8500x; 1.1520x over previous
#include <cuda_runtime.h>

// GlobalAggregator: B=128, N=512, K=12, DIM=128
// Warp-per-(b,n) for phases A-D; CTA-cooperative Phase E.

#define KK 12
#define DIMD 128
#define FF 129           // DIM+1
#define ROWS 16          // feat row stride in floats (64B, swizzled quads)

__device__ __forceinline__ unsigned long long dup2(float x) {
    unsigned long long r;
    asm("mov.b64 %0, {%1, %1};" : "=l"(r) : "f"(x));
    return r;
}
__device__ __forceinline__ void fma2(unsigned long long& acc, unsigned long long a, unsigned long long b) {
    asm("fma.rn.f32x2 %0, %1, %2, %0;" : "+l"(acc) : "l"(a), "l"(b));
}
__device__ __forceinline__ float lo32(unsigned long long v) {
    return __uint_as_float((unsigned)(v & 0xffffffffULL));
}
__device__ __forceinline__ float hi32(unsigned long long v) {
    return __uint_as_float((unsigned)(v >> 32));
}
__device__ __forceinline__ float lrelu(float x) {
    return fmaxf(x, 0.f) + 0.2f * fminf(x, 0.f);
}

__global__ __launch_bounds__(128, 5) void gat_warp_kernel(
    const float* __restrict__ self_v,   // [B,N,DIM]
    const float* __restrict__ neigh,    // [B,N,K,DIM]
    const float* __restrict__ nw,       // [B,N,K]
    const float* __restrict__ extra,    // [B,N,DIM]
    const float* __restrict__ w1,       // [129,128]
    const float* __restrict__ w2,       // [128]
    const float* __restrict__ w3,       // [256,128]
    float* __restrict__ out)            // [B,N,DIM]
{
    __shared__ __align__(16) float feat_sh[4][(FF + 1) * ROWS]; // per-warp 8320B
    __shared__ __align__(16) float catp[2 * DIMD * 4];          // [f][bn] interleaved

    const int warp = threadIdx.x >> 5;
    const int lane = threadIdx.x & 31;
    const int bn0 = blockIdx.x * 4;
    const int bn = bn0 + warp;

    float* feat_s = feat_sh[warp];
    const float4* nb4 = (const float4*)(neigh + (size_t)bn * KK * DIMD);

    // ---- Phase A: feat rows f = 4*lane..4*lane+3 (k = 0..11), swizzled quads.
    // neigh/extra are streaming -> evict-first so w1/w3 stay L1-resident.
    {
        float4 ex = __ldcs((const float4*)(extra + (size_t)bn * DIMD) + lane);
        float rows[4][KK];
#pragma unroll
        for (int k = 0; k < KK; k++) {
            float4 v = __ldcs(nb4 + k * 32 + lane);
            rows[0][k] = ex.x * v.x;
            rows[1][k] = ex.y * v.y;
            rows[2][k] = ex.z * v.z;
            rows[3][k] = ex.w * v.w;
        }
#pragma unroll
        for (int j = 0; j < 4; j++) {
            int f = 4 * lane + j;
#pragma unroll
            for (int c = 0; c < 3; c++) {
                int cp = (c + lane) & 3;   // swizzle key = f>>2 = lane
                *(float4*)&feat_s[f * ROWS + 4 * cp] =
                    make_float4(rows[j][4 * c], rows[j][4 * c + 1],
                                rows[j][4 * c + 2], rows[j][4 * c + 3]);
            }
        }
        if (lane < KK)  // row f=128: swizzle key 0 -> identity
            feat_s[DIMD * ROWS + lane] = __ldcs(nw + (size_t)bn * KK + lane);
    }
    __syncwarp();

    // ---- Phase B: alpha_pre[k][d] = sum_f feat[f][k] * w1[f][d], d = 4*lane+j
    unsigned long long acc[4][6];
#pragma unroll
    for (int j = 0; j < 4; j++)
#pragma unroll
        for (int p = 0; p < 6; p++) acc[j][p] = 0ULL;

    const float4* w1r = (const float4*)w1 + lane;   // w1[f][4*lane..] (L1-resident)
#pragma unroll 2
    for (int f = 0; f < FF; f++) {
        float4 wv = __ldg(&w1r[f * 32]);
        int g = (f >> 2) & 3;
        const float* row = feat_s + f * ROWS;
        ulonglong2 qa = *(const ulonglong2*)(row + 4 * ((0 + g) & 3)); // k0..3
        ulonglong2 qb = *(const ulonglong2*)(row + 4 * ((1 + g) & 3)); // k4..7
        ulonglong2 qc = *(const ulonglong2*)(row + 4 * ((2 + g) & 3)); // k8..11
        unsigned long long w0 = dup2(wv.x), w1d = dup2(wv.y),
                           w2d = dup2(wv.z), w3d = dup2(wv.w);
        fma2(acc[0][0], qa.x, w0);  fma2(acc[0][1], qa.y, w0);
        fma2(acc[0][2], qb.x, w0);  fma2(acc[0][3], qb.y, w0);
        fma2(acc[0][4], qc.x, w0);  fma2(acc[0][5], qc.y, w0);
        fma2(acc[1][0], qa.x, w1d); fma2(acc[1][1], qa.y, w1d);
        fma2(acc[1][2], qb.x, w1d); fma2(acc[1][3], qb.y, w1d);
        fma2(acc[1][4], qc.x, w1d); fma2(acc[1][5], qc.y, w1d);
        fma2(acc[2][0], qa.x, w2d); fma2(acc[2][1], qa.y, w2d);
        fma2(acc[2][2], qb.x, w2d); fma2(acc[2][3], qb.y, w2d);
        fma2(acc[2][4], qc.x, w2d); fma2(acc[2][5], qc.y, w2d);
        fma2(acc[3][0], qa.x, w3d); fma2(acc[3][1], qa.y, w3d);
        fma2(acc[3][2], qb.x, w3d); fma2(acc[3][3], qb.y, w3d);
        fma2(acc[3][4], qc.x, w3d); fma2(acc[3][5], qc.y, w3d);
    }

    // ---- Phase C: leaky_relu, dot w2 (reduce over d), softmax over k (per-lane)
    float s[KK];
    {
        float4 w2v = *((const float4*)w2 + lane);
        float wj[4] = {w2v.x, w2v.y, w2v.z, w2v.w};
#pragma unroll
        for (int p = 0; p < 6; p++) {
            float slo = 0.f, shi = 0.f;
#pragma unroll
            for (int j = 0; j < 4; j++) {
                slo += lrelu(lo32(acc[j][p])) * wj[j];
                shi += lrelu(hi32(acc[j][p])) * wj[j];
            }
            s[2 * p] = slo;
            s[2 * p + 1] = shi;
        }
    }
#pragma unroll
    for (int k = 0; k < KK; k++) {
#pragma unroll
        for (int off = 16; off > 0; off >>= 1)
            s[k] += __shfl_xor_sync(0xffffffffu, s[k], off);
    }
    float alpha[KK];
    {
        float m = s[0];
#pragma unroll
        for (int k = 1; k < KK; k++) m = fmaxf(m, s[k]);
        float tot = 0.f;
#pragma unroll
        for (int k = 0; k < KK; k++) {
            alpha[k] = __expf(s[k] - m);
            tot += alpha[k];
        }
        float inv = 1.f / tot;
#pragma unroll
        for (int k = 0; k < KK; k++) alpha[k] *= inv;
    }

    // ---- Phase D: agg = sum_k alpha[k]*neigh[k][:]; cat stored [f][bn] interleaved
    {
        float4 agg = make_float4(0.f, 0.f, 0.f, 0.f);
#pragma unroll
        for (int k = 0; k < KK; k++) {
            float4 v = __ldcs(nb4 + k * 32 + lane);   // L2 hit (just streamed)
            agg.x = fmaf(alpha[k], v.x, agg.x);
            agg.y = fmaf(alpha[k], v.y, agg.y);
            agg.z = fmaf(alpha[k], v.z, agg.z);
            agg.w = fmaf(alpha[k], v.w, agg.w);
        }
        float4 sv = __ldcs((const float4*)(self_v + (size_t)bn * DIMD) + lane);
        float aj[4] = {agg.x, agg.y, agg.z, agg.w};
        float svj[4] = {sv.x, sv.y, sv.z, sv.w};
#pragma unroll
        for (int j = 0; j < 4; j++) {
            catp[(4 * lane + j) * 4 + warp] = svj[j];
            catp[(DIMD + 4 * lane + j) * 4 + warp] = aj[j];
        }
    }
    __syncthreads();

    // ---- Phase E (CTA-cooperative): lane owns out column c for all 4 bn.
    // out[bn][c] = relu( sum_f catp[f][bn] * w3[f][c] )
    {
        const int c = 32 * warp + lane;
        unsigned long long a01 = 0ULL, a23 = 0ULL;
        unsigned long long b01 = 0ULL, b23 = 0ULL;
        const float* w3c = w3 + c;
#pragma unroll 8
        for (int f = 0; f < 2 * DIMD; f += 2) {
            float wv0 = __ldg(w3c + f * DIMD);
            float wv1 = __ldg(w3c + (f + 1) * DIMD);
            ulonglong2 q0 = *(const ulonglong2*)&catp[4 * f];        // (c0,c1),(c2,c3)
            ulonglong2 q1 = *(const ulonglong2*)&catp[4 * (f + 1)];
            unsigned long long wd0 = dup2(wv0);
            unsigned long long wd1 = dup2(wv1);
            fma2(a01, q0.x, wd0); fma2(a23, q0.y, wd0);
            fma2(b01, q1.x, wd1); fma2(b23, q1.y, wd1);
        }
        float o0 = fmaxf(lo32(a01) + lo32(b01), 0.f);
        float o1 = fmaxf(hi32(a01) + hi32(b01), 0.f);
        float o2 = fmaxf(lo32(a23) + lo32(b23), 0.f);
        float o3 = fmaxf(hi32(a23) + hi32(b23), 0.f);
        float* ob = out + (size_t)bn0 * DIMD + c;
        ob[0 * DIMD] = o0;
        ob[1 * DIMD] = o1;
        ob[2 * DIMD] = o2;
        ob[3 * DIMD] = o3;
    }
}

extern "C" void kernel_launch(void* const* d_in, const int* in_sizes, int n_in,
                              void* d_out, int out_size) {
    const float* self_v = (const float*)d_in[0];
    const float* neigh  = (const float*)d_in[1];
    const float* nw     = (const float*)d_in[2];
    const float* extra  = (const float*)d_in[3];
    const float* w1     = (const float*)d_in[6];
    const float* w2     = (const float*)d_in[7];
    const float* w3     = (const float*)d_in[8];
    float* out = (float*)d_out;

    gat_warp_kernel<<<(128 * 512) / 4, 128>>>(self_v, neigh, nw, extra, w1, w2, w3, out);
}

// round 5
// speedup vs baseline: 2.8612x; 1.5466x over previous
#include <cuda_runtime.h>
#include <cstdint>

// GlobalAggregator: B=128,N=512,K=12,DIM=128
//  gemm1 (mma.sync bf16 3-pass): scores[bnk] = lrelu((neigh*extra)@w1 + nw*w1[128,:]) @ w2
//  finish (scalar): softmax_k, agg, concat, @w3, relu

#define KK 12
#define DIMD 128
#define BN_TOTAL (128 * 512)
#define M_ROWS (BN_TOTAL * KK)   // 786432
#define TILE_M 256
#define NT_G (M_ROWS / TILE_M)   // 3072
#define GRID_G 148

__device__ float g_scores[M_ROWS];

// ---- helpers ----
__device__ __forceinline__ uint32_t packbf(float lo, float hi) {
    uint32_t r;
    asm("cvt.rn.bf16x2.f32 %0, %1, %2;" : "=r"(r) : "f"(hi), "f"(lo));
    return r;
}
__device__ __forceinline__ float bflo(uint32_t p) { return __uint_as_float(p << 16); }
__device__ __forceinline__ float bfhi(uint32_t p) { return __uint_as_float(p & 0xffff0000u); }

__device__ __forceinline__ void mma16816(float c[4],
                                         uint32_t a0, uint32_t a1, uint32_t a2, uint32_t a3,
                                         uint32_t b0, uint32_t b1) {
    asm volatile("mma.sync.aligned.m16n8k16.row.col.f32.bf16.bf16.f32 "
                 "{%0,%1,%2,%3},{%4,%5,%6,%7},{%8,%9},{%0,%1,%2,%3};"
                 : "+f"(c[0]), "+f"(c[1]), "+f"(c[2]), "+f"(c[3])
                 : "r"(a0), "r"(a1), "r"(a2), "r"(a3), "r"(b0), "r"(b1));
}

// ---------------- gemm1: persistent HMMA kernel ----------------
// smem: [0,65536) B fragments (hi0,hi1,lo0,lo1 per lane per (kt,nt) block)
//       [65536, 65536+1024) packed (w1last0, w1last1, w2_0, w2_1) per (nt,tg)
__global__ __launch_bounds__(256, 1) void gemm1_kernel(
    const float* __restrict__ neigh,
    const float* __restrict__ nw,
    const float* __restrict__ extra,
    const float* __restrict__ w1,
    const float* __restrict__ w2) {
    extern __shared__ __align__(16) char smem[];
    uint4* bfrag = (uint4*)smem;
    float4* w1w2 = (float4*)(smem + 65536);

    const int tid = threadIdx.x, wid = tid >> 5, lane = tid & 31;
    const int g = lane >> 2, tg = lane & 3;

    // ---- setup: B fragments from w1 (col-major frag: b0 = k{2tg,2tg+1}, b1 = k{+8,+9}, col n)
    for (int bi = wid; bi < 128; bi += 8) {
        int kt = bi >> 4, nt = bi & 15;
        int n = nt * 8 + g;
        int k0 = kt * 16 + tg * 2;
        float v0 = __ldg(w1 + k0 * DIMD + n);
        float v1 = __ldg(w1 + (k0 + 1) * DIMD + n);
        float v2 = __ldg(w1 + (k0 + 8) * DIMD + n);
        float v3 = __ldg(w1 + (k0 + 9) * DIMD + n);
        uint32_t h0 = packbf(v0, v1), h1 = packbf(v2, v3);
        uint32_t l0 = packbf(v0 - bflo(h0), v1 - bfhi(h0));
        uint32_t l1 = packbf(v2 - bflo(h1), v3 - bfhi(h1));
        bfrag[bi * 32 + lane] = make_uint4(h0, h1, l0, l1);
    }
    if (tid < 64) {
        int nt = tid >> 2, tq = tid & 3;
        int c0 = nt * 8 + tq * 2;
        w1w2[tid] = make_float4(__ldg(w1 + 128 * DIMD + c0),
                                __ldg(w1 + 128 * DIMD + c0 + 1),
                                __ldg(w2 + c0), __ldg(w2 + c0 + 1));
    }
    __syncthreads();

    for (int tile = blockIdx.x; tile < NT_G; tile += GRID_G) {
        const int base = tile * TILE_M + wid * 32;
        const float* nr[4];
        const float* er[4];
        float nwv[4];
        int rw[4];
#pragma unroll
        for (int j = 0; j < 4; j++) {       // rows g, g+8, g+16, g+24
            int r = base + g + 8 * j;
            rw[j] = r;
            nr[j] = neigh + (size_t)r * DIMD;
            er[j] = extra + (size_t)(r / KK) * DIMD;
            nwv[j] = __ldg(nw + r);
        }

        float acc[2][16][4];
#pragma unroll
        for (int mt = 0; mt < 2; mt++)
#pragma unroll
            for (int nt = 0; nt < 16; nt++)
#pragma unroll
                for (int q = 0; q < 4; q++) acc[mt][nt][q] = 0.f;

#pragma unroll 1
        for (int kt = 0; kt < 8; kt++) {
            const int c0 = kt * 16 + tg * 2;
            uint32_t ah[2][4], al[2][4];
#pragma unroll
            for (int j = 0; j < 4; j++) {
                int mt = j >> 1, rh = j & 1;
#pragma unroll
                for (int half = 0; half < 2; half++) {
                    float2 nv = __ldcs((const float2*)(nr[j] + c0 + 8 * half));
                    float2 ev = *(const float2*)(er[j] + c0 + 8 * half);
                    float x0 = nv.x * ev.x, x1 = nv.y * ev.y;
                    uint32_t h = packbf(x0, x1);
                    uint32_t l = packbf(x0 - bflo(h), x1 - bfhi(h));
                    int ai = rh + 2 * half;  // a0:r,h0  a1:r+8,h0  a2:r,h1  a3:r+8,h1
                    ah[mt][ai] = h;
                    al[mt][ai] = l;
                }
            }
#pragma unroll
            for (int nt = 0; nt < 16; nt++) {
                uint4 bq = bfrag[(kt * 16 + nt) * 32 + lane];
#pragma unroll
                for (int mt = 0; mt < 2; mt++) {
                    mma16816(acc[mt][nt], ah[mt][0], ah[mt][1], ah[mt][2], ah[mt][3], bq.x, bq.y);
                    mma16816(acc[mt][nt], al[mt][0], al[mt][1], al[mt][2], al[mt][3], bq.x, bq.y);
                    mma16816(acc[mt][nt], ah[mt][0], ah[mt][1], ah[mt][2], ah[mt][3], bq.z, bq.w);
                }
            }
        }

        // ---- epilogue: rowsum[j] = sum_n w2[n]*lrelu(D[row_j][n] + nw*w1last[n])
        float rowsum[4] = {0.f, 0.f, 0.f, 0.f};
#pragma unroll
        for (int nt = 0; nt < 16; nt++) {
            float4 ww = w1w2[nt * 4 + tg];   // cols nt*8+2tg, +1
#pragma unroll
            for (int mt = 0; mt < 2; mt++) {
#pragma unroll
                for (int rh = 0; rh < 2; rh++) {
                    int j = mt * 2 + rh;
                    float v0 = acc[mt][nt][rh * 2 + 0] + nwv[j] * ww.x;
                    float v1 = acc[mt][nt][rh * 2 + 1] + nwv[j] * ww.y;
                    v0 = fmaxf(v0, 0.f) + 0.2f * fminf(v0, 0.f);
                    v1 = fmaxf(v1, 0.f) + 0.2f * fminf(v1, 0.f);
                    rowsum[j] = fmaf(v0, ww.z, fmaf(v1, ww.w, rowsum[j]));
                }
            }
        }
#pragma unroll
        for (int j = 0; j < 4; j++) {
            rowsum[j] += __shfl_xor_sync(0xffffffffu, rowsum[j], 1);
            rowsum[j] += __shfl_xor_sync(0xffffffffu, rowsum[j], 2);
        }
        if (tg == 0) {
#pragma unroll
            for (int j = 0; j < 4; j++) g_scores[rw[j]] = rowsum[j];
        }
    }
}

// ---------------- finish kernel (softmax + agg + w3 GEMM) ----------------
__device__ __forceinline__ unsigned long long dup2(float x) {
    unsigned long long r;
    asm("mov.b64 %0, {%1, %1};" : "=l"(r) : "f"(x));
    return r;
}
__device__ __forceinline__ void fma2(unsigned long long& acc, unsigned long long a, unsigned long long b) {
    asm("fma.rn.f32x2 %0, %1, %2, %0;" : "+l"(acc) : "l"(a), "l"(b));
}
__device__ __forceinline__ float lo32(unsigned long long v) { return __uint_as_float((unsigned)(v & 0xffffffffULL)); }
__device__ __forceinline__ float hi32(unsigned long long v) { return __uint_as_float((unsigned)(v >> 32)); }

__global__ __launch_bounds__(128, 8) void finish_kernel(
    const float* __restrict__ self_v,
    const float* __restrict__ neigh,
    const float* __restrict__ w3,
    float* __restrict__ out) {
    __shared__ __align__(16) float catp[2 * DIMD * 4];   // [f][bn] interleaved

    const int warp = threadIdx.x >> 5;
    const int lane = threadIdx.x & 31;
    const int bn0 = blockIdx.x * 4;
    const int bn = bn0 + warp;

    const float4* nb4 = (const float4*)(neigh + (size_t)bn * KK * DIMD);

    float alpha[KK];
    {
        float s[KK];
#pragma unroll
        for (int k = 0; k < KK; k++) s[k] = __ldg(&g_scores[(size_t)bn * KK + k]);
        float mx = s[0];
#pragma unroll
        for (int k = 1; k < KK; k++) mx = fmaxf(mx, s[k]);
        float tot = 0.f;
#pragma unroll
        for (int k = 0; k < KK; k++) { alpha[k] = __expf(s[k] - mx); tot += alpha[k]; }
        float inv = 1.f / tot;
#pragma unroll
        for (int k = 0; k < KK; k++) alpha[k] *= inv;
    }

    {
        float4 agg = make_float4(0.f, 0.f, 0.f, 0.f);
#pragma unroll
        for (int k = 0; k < KK; k++) {
            float4 v = __ldcs(nb4 + k * 32 + lane);
            agg.x = fmaf(alpha[k], v.x, agg.x);
            agg.y = fmaf(alpha[k], v.y, agg.y);
            agg.z = fmaf(alpha[k], v.z, agg.z);
            agg.w = fmaf(alpha[k], v.w, agg.w);
        }
        float4 sv = __ldcs((const float4*)(self_v + (size_t)bn * DIMD) + lane);
        float aj[4] = {agg.x, agg.y, agg.z, agg.w};
        float svj[4] = {sv.x, sv.y, sv.z, sv.w};
#pragma unroll
        for (int j = 0; j < 4; j++) {
            catp[(4 * lane + j) * 4 + warp] = svj[j];
            catp[(DIMD + 4 * lane + j) * 4 + warp] = aj[j];
        }
    }
    __syncthreads();

    {
        const int c = 32 * warp + lane;
        unsigned long long a01 = 0ULL, a23 = 0ULL, b01 = 0ULL, b23 = 0ULL;
        const float* w3c = w3 + c;
#pragma unroll 8
        for (int f = 0; f < 2 * DIMD; f += 2) {
            float wv0 = __ldg(w3c + f * DIMD);
            float wv1 = __ldg(w3c + (f + 1) * DIMD);
            ulonglong2 q0 = *(const ulonglong2*)&catp[4 * f];
            ulonglong2 q1 = *(const ulonglong2*)&catp[4 * (f + 1)];
            unsigned long long wd0 = dup2(wv0), wd1 = dup2(wv1);
            fma2(a01, q0.x, wd0); fma2(a23, q0.y, wd0);
            fma2(b01, q1.x, wd1); fma2(b23, q1.y, wd1);
        }
        float o0 = fmaxf(lo32(a01) + lo32(b01), 0.f);
        float o1 = fmaxf(hi32(a01) + hi32(b01), 0.f);
        float o2 = fmaxf(lo32(a23) + lo32(b23), 0.f);
        float o3 = fmaxf(hi32(a23) + hi32(b23), 0.f);
        float* ob = out + (size_t)bn0 * DIMD + c;
        ob[0 * DIMD] = o0;
        ob[1 * DIMD] = o1;
        ob[2 * DIMD] = o2;
        ob[3 * DIMD] = o3;
    }
}

// ---------------- launch ----------------
extern "C" void kernel_launch(void* const* d_in, const int* in_sizes, int n_in,
                              void* d_out, int out_size) {
    const float* self_v = (const float*)d_in[0];
    const float* neigh  = (const float*)d_in[1];
    const float* nw     = (const float*)d_in[2];
    const float* extra  = (const float*)d_in[3];
    const float* w1     = (const float*)d_in[6];
    const float* w2     = (const float*)d_in[7];
    const float* w3     = (const float*)d_in[8];
    float* out = (float*)d_out;

    static bool attr_set = false;
    if (!attr_set) {
        cudaFuncSetAttribute(gemm1_kernel, cudaFuncAttributeMaxDynamicSharedMemorySize, 66560);
        attr_set = true;
    }

    gemm1_kernel<<<GRID_G, 256, 66560>>>(neigh, nw, extra, w1, w2);
    finish_kernel<<<BN_TOTAL / 4, 128>>>(self_v, neigh, w3, out);
}

// round 6
// speedup vs baseline: 3.7617x; 1.3147x over previous
#include <cuda_runtime.h>
#include <cstdint>

// GlobalAggregator: B=128,N=512,K=12,DIM=128
//  gemm1 (mma.sync f16 single-pass): scores = lrelu((neigh*extra)@w1 + nw*w1[128,:]) @ w2
//  finish (scalar): softmax_k, agg, concat, @w3, relu

#define KK 12
#define DIMD 128
#define BN_TOTAL (128 * 512)
#define M_ROWS (BN_TOTAL * KK)   // 786432
#define TILE_M 128
#define NT_G (M_ROWS / TILE_M)   // 6144
#define GRID_G 296

__device__ float g_scores[M_ROWS];

// ---- helpers ----
__device__ __forceinline__ uint32_t packh(float lo, float hi) {
    uint32_t r;
    asm("cvt.rn.f16x2.f32 %0, %1, %2;" : "=r"(r) : "f"(hi), "f"(lo));
    return r;
}
__device__ __forceinline__ void mma16816h(float c[4],
                                          uint32_t a0, uint32_t a1, uint32_t a2, uint32_t a3,
                                          uint32_t b0, uint32_t b1) {
    asm volatile("mma.sync.aligned.m16n8k16.row.col.f32.f16.f16.f32 "
                 "{%0,%1,%2,%3},{%4,%5,%6,%7},{%8,%9},{%0,%1,%2,%3};"
                 : "+f"(c[0]), "+f"(c[1]), "+f"(c[2]), "+f"(c[3])
                 : "r"(a0), "r"(a1), "r"(a2), "r"(a3), "r"(b0), "r"(b1));
}

// ---------------- gemm1: persistent HMMA kernel (fp16 single-pass) ----------------
__global__ __launch_bounds__(256, 2) void gemm1_kernel(
    const float* __restrict__ neigh,
    const float* __restrict__ nw,
    const float* __restrict__ extra,
    const float* __restrict__ w1,
    const float* __restrict__ w2) {
    __shared__ __align__(16) uint2 bfrag[128 * 32];   // 32 KB: (kt,nt) fp16 B frags
    __shared__ __align__(16) float4 w1w2[64];         // (w1last pair, w2 pair) per (nt,tg)

    const int tid = threadIdx.x, wid = tid >> 5, lane = tid & 31;
    const int g = lane >> 2, tg = lane & 3;

    // ---- setup: B fragments from w1 (col-major: b0 = k{2tg,2tg+1}, b1 = k{+8,+9}, col n)
    for (int bi = wid; bi < 128; bi += 8) {
        int kt = bi >> 4, nt = bi & 15;
        int n = nt * 8 + g;
        int k0 = kt * 16 + tg * 2;
        float v0 = __ldg(w1 + k0 * DIMD + n);
        float v1 = __ldg(w1 + (k0 + 1) * DIMD + n);
        float v2 = __ldg(w1 + (k0 + 8) * DIMD + n);
        float v3 = __ldg(w1 + (k0 + 9) * DIMD + n);
        bfrag[bi * 32 + lane] = make_uint2(packh(v0, v1), packh(v2, v3));
    }
    if (tid < 64) {
        int nt = tid >> 2, tq = tid & 3;
        int c0 = nt * 8 + tq * 2;
        w1w2[tid] = make_float4(__ldg(w1 + 128 * DIMD + c0),
                                __ldg(w1 + 128 * DIMD + c0 + 1),
                                __ldg(w2 + c0), __ldg(w2 + c0 + 1));
    }
    __syncthreads();

    for (int tile = blockIdx.x; tile < NT_G; tile += GRID_G) {
        const int base = tile * TILE_M + wid * 16;
        const int r0 = base + g, r1 = r0 + 8;
        const float* nr[2] = {neigh + (size_t)r0 * DIMD, neigh + (size_t)r1 * DIMD};
        const float* er[2] = {extra + (size_t)(r0 / KK) * DIMD, extra + (size_t)(r1 / KK) * DIMD};
        const float nwv[2] = {__ldg(nw + r0), __ldg(nw + r1)};

        float acc[16][4];
#pragma unroll
        for (int nt = 0; nt < 16; nt++)
#pragma unroll
            for (int q = 0; q < 4; q++) acc[nt][q] = 0.f;

#pragma unroll 1
        for (int kt = 0; kt < 8; kt++) {
            const int c0 = kt * 16 + tg * 2;
            uint32_t a[4];
#pragma unroll
            for (int j = 0; j < 2; j++) {
#pragma unroll
                for (int half = 0; half < 2; half++) {
                    float2 nv = __ldcs((const float2*)(nr[j] + c0 + 8 * half));
                    float2 ev = *(const float2*)(er[j] + c0 + 8 * half);
                    a[j + 2 * half] = packh(nv.x * ev.x, nv.y * ev.y);
                }
            }
#pragma unroll
            for (int nt = 0; nt < 16; nt++) {
                uint2 bq = bfrag[(kt * 16 + nt) * 32 + lane];
                mma16816h(acc[nt], a[0], a[1], a[2], a[3], bq.x, bq.y);
            }
        }

        // ---- epilogue: rowsum[j] = sum_n w2[n]*lrelu(D[row_j][n] + nw*w1last[n])
        float rowsum[2] = {0.f, 0.f};
#pragma unroll
        for (int nt = 0; nt < 16; nt++) {
            float4 ww = w1w2[nt * 4 + tg];
#pragma unroll
            for (int rh = 0; rh < 2; rh++) {
                float v0 = acc[nt][rh * 2 + 0] + nwv[rh] * ww.x;
                float v1 = acc[nt][rh * 2 + 1] + nwv[rh] * ww.y;
                v0 = fmaxf(v0, 0.f) + 0.2f * fminf(v0, 0.f);
                v1 = fmaxf(v1, 0.f) + 0.2f * fminf(v1, 0.f);
                rowsum[rh] = fmaf(v0, ww.z, fmaf(v1, ww.w, rowsum[rh]));
            }
        }
#pragma unroll
        for (int j = 0; j < 2; j++) {
            rowsum[j] += __shfl_xor_sync(0xffffffffu, rowsum[j], 1);
            rowsum[j] += __shfl_xor_sync(0xffffffffu, rowsum[j], 2);
        }
        if (tg == 0) {
            g_scores[r0] = rowsum[0];
            g_scores[r1] = rowsum[1];
        }
    }
}

// ---------------- finish kernel (softmax + agg + w3 GEMM) ----------------
#define FP 12   // catp row pad (floats): 48B rows keep 16B alignment, tolerable STS conflicts

__device__ __forceinline__ unsigned long long dup2(float x) {
    unsigned long long r;
    asm("mov.b64 %0, {%1, %1};" : "=l"(r) : "f"(x));
    return r;
}
__device__ __forceinline__ void fma2(unsigned long long& acc, unsigned long long a, unsigned long long b) {
    asm("fma.rn.f32x2 %0, %1, %2, %0;" : "+l"(acc) : "l"(a), "l"(b));
}
__device__ __forceinline__ float lo32(unsigned long long v) { return __uint_as_float((unsigned)(v & 0xffffffffULL)); }
__device__ __forceinline__ float hi32(unsigned long long v) { return __uint_as_float((unsigned)(v >> 32)); }

__global__ __launch_bounds__(256) void finish_kernel(
    const float* __restrict__ self_v,
    const float* __restrict__ neigh,
    const float* __restrict__ w3,
    float* __restrict__ out) {
    __shared__ __align__(16) float catp[2 * DIMD * FP];   // [f][12-pad], cols 0..7 = bn
    __shared__ float part[DIMD * 9];                      // h=1 partials, pad 9 (conflict-free)

    const int tid = threadIdx.x;
    const int wid = tid >> 5;
    const int lane = tid & 31;
    const int bn0 = blockIdx.x * 8;
    const int bn = bn0 + wid;

    // ---- alpha (per-warp bn, replicated per lane)
    float alpha[KK];
    {
        float s[KK];
#pragma unroll
        for (int k = 0; k < KK; k++) s[k] = __ldg(&g_scores[(size_t)bn * KK + k]);
        float mx = s[0];
#pragma unroll
        for (int k = 1; k < KK; k++) mx = fmaxf(mx, s[k]);
        float tot = 0.f;
#pragma unroll
        for (int k = 0; k < KK; k++) { alpha[k] = __expf(s[k] - mx); tot += alpha[k]; }
        float inv = 1.f / tot;
#pragma unroll
        for (int k = 0; k < KK; k++) alpha[k] *= inv;
    }

    // ---- agg + cat store (lane owns cols 4lane..4lane+3 of its bn)
    {
        const float4* nb4 = (const float4*)(neigh + (size_t)bn * KK * DIMD);
        float4 agg = make_float4(0.f, 0.f, 0.f, 0.f);
#pragma unroll
        for (int k = 0; k < KK; k++) {
            float4 v = __ldcs(nb4 + k * 32 + lane);
            agg.x = fmaf(alpha[k], v.x, agg.x);
            agg.y = fmaf(alpha[k], v.y, agg.y);
            agg.z = fmaf(alpha[k], v.z, agg.z);
            agg.w = fmaf(alpha[k], v.w, agg.w);
        }
        float4 sv = __ldcs((const float4*)(self_v + (size_t)bn * DIMD) + lane);
        float aj[4] = {agg.x, agg.y, agg.z, agg.w};
        float svj[4] = {sv.x, sv.y, sv.z, sv.w};
#pragma unroll
        for (int j = 0; j < 4; j++) {
            catp[(4 * lane + j) * FP + wid] = svj[j];
            catp[(DIMD + 4 * lane + j) * FP + wid] = aj[j];
        }
    }
    __syncthreads();

    // ---- Phase E: thread = (column c, f-half h). acc over its 128 f for 8 bn.
    const int c = tid & 127;
    const int h = tid >> 7;
    unsigned long long a01 = 0ULL, a23 = 0ULL, a45 = 0ULL, a67 = 0ULL;
    {
        const float* w3c = w3 + (size_t)h * DIMD * DIMD + c;
        const float* cp = catp + h * DIMD * FP;
#pragma unroll 4
        for (int f = 0; f < DIMD; f++) {
            float wv = __ldg(w3c + f * DIMD);
            unsigned long long wd = dup2(wv);
            ulonglong2 q0 = *(const ulonglong2*)(cp + f * FP);       // bn 0..3
            ulonglong2 q1 = *(const ulonglong2*)(cp + f * FP + 4);   // bn 4..7
            fma2(a01, q0.x, wd); fma2(a23, q0.y, wd);
            fma2(a45, q1.x, wd); fma2(a67, q1.y, wd);
        }
    }
    if (h) {
        part[c * 9 + 0] = lo32(a01); part[c * 9 + 1] = hi32(a01);
        part[c * 9 + 2] = lo32(a23); part[c * 9 + 3] = hi32(a23);
        part[c * 9 + 4] = lo32(a45); part[c * 9 + 5] = hi32(a45);
        part[c * 9 + 6] = lo32(a67); part[c * 9 + 7] = hi32(a67);
    }
    __syncthreads();
    if (!h) {
        float o[8];
        o[0] = lo32(a01) + part[c * 9 + 0];
        o[1] = hi32(a01) + part[c * 9 + 1];
        o[2] = lo32(a23) + part[c * 9 + 2];
        o[3] = hi32(a23) + part[c * 9 + 3];
        o[4] = lo32(a45) + part[c * 9 + 4];
        o[5] = hi32(a45) + part[c * 9 + 5];
        o[6] = lo32(a67) + part[c * 9 + 6];
        o[7] = hi32(a67) + part[c * 9 + 7];
#pragma unroll
        for (int j = 0; j < 8; j++)
            out[(size_t)(bn0 + j) * DIMD + c] = fmaxf(o[j], 0.f);
    }
}

// ---------------- launch ----------------
extern "C" void kernel_launch(void* const* d_in, const int* in_sizes, int n_in,
                              void* d_out, int out_size) {
    const float* self_v = (const float*)d_in[0];
    const float* neigh  = (const float*)d_in[1];
    const float* nw     = (const float*)d_in[2];
    const float* extra  = (const float*)d_in[3];
    const float* w1     = (const float*)d_in[6];
    const float* w2     = (const float*)d_in[7];
    const float* w3     = (const float*)d_in[8];
    float* out = (float*)d_out;

    gemm1_kernel<<<GRID_G, 256>>>(neigh, nw, extra, w1, w2);
    finish_kernel<<<BN_TOTAL / 8, 256>>>(self_v, neigh, w3, out);
}

// round 7
// speedup vs baseline: 5.3547x; 1.4235x over previous
#include <cuda_runtime.h>
#include <cstdint>

// GlobalAggregator fused: B=128,N=512,K=12,DIM=128.
// CTA = 8 warps = 8 bn. Per warp: gemm1 (HMMA) -> scores -> softmax -> agg;
// then CTA-wide w3 GEMM on HMMA from fp16 cat in smem. neigh read ONCE.

#define KK 12
#define DIMD 128
#define BN_TOTAL (128 * 512)

__device__ uint2 g_bfrag1[128 * 32];   // w1 fragments: (kt0..7, nt0..15, lane)
__device__ uint2 g_bfrag3[256 * 32];   // w3 fragments: (kt0..15, nt0..15, lane)
__device__ float4 g_w1w2[64];          // (w1last pair, w2 pair) per (nt, tg)

// ---- helpers ----
__device__ __forceinline__ uint32_t packh(float lo, float hi) {
    uint32_t r;
    asm("cvt.rn.f16x2.f32 %0, %1, %2;" : "=r"(r) : "f"(hi), "f"(lo));
    return r;
}
__device__ __forceinline__ void mma16816h(float c[4],
                                          uint32_t a0, uint32_t a1, uint32_t a2, uint32_t a3,
                                          uint32_t b0, uint32_t b1) {
    asm volatile("mma.sync.aligned.m16n8k16.row.col.f32.f16.f16.f32 "
                 "{%0,%1,%2,%3},{%4,%5,%6,%7},{%8,%9},{%0,%1,%2,%3};"
                 : "+f"(c[0]), "+f"(c[1]), "+f"(c[2]), "+f"(c[3])
                 : "r"(a0), "r"(a1), "r"(a2), "r"(a3), "r"(b0), "r"(b1));
}

// ---------------- prep: bake B fragments ----------------
__global__ void prep_kernel(const float* __restrict__ w1,
                            const float* __restrict__ w2,
                            const float* __restrict__ w3) {
    int idx = blockIdx.x * 256 + threadIdx.x;
    if (idx < 4096) {                       // w1 frags (128 groups)
        int gi = idx >> 5, lane = idx & 31;
        int kt = gi >> 4, nt = gi & 15;
        int g = lane >> 2, tg = lane & 3;
        int n = nt * 8 + g, k0 = kt * 16 + tg * 2;
        float v0 = w1[k0 * DIMD + n],       v1 = w1[(k0 + 1) * DIMD + n];
        float v2 = w1[(k0 + 8) * DIMD + n], v3 = w1[(k0 + 9) * DIMD + n];
        g_bfrag1[idx] = make_uint2(packh(v0, v1), packh(v2, v3));
    } else if (idx < 4096 + 8192) {         // w3 frags (256 groups, K=256)
        int j = idx - 4096;
        int gi = j >> 5, lane = j & 31;
        int kt = gi >> 4, nt = gi & 15;
        int g = lane >> 2, tg = lane & 3;
        int n = nt * 8 + g, k0 = kt * 16 + tg * 2;
        float v0 = w3[k0 * DIMD + n],       v1 = w3[(k0 + 1) * DIMD + n];
        float v2 = w3[(k0 + 8) * DIMD + n], v3 = w3[(k0 + 9) * DIMD + n];
        g_bfrag3[j] = make_uint2(packh(v0, v1), packh(v2, v3));
    } else if (idx < 4096 + 8192 + 64) {    // w1last / w2 pairs
        int t = idx - 4096 - 8192;
        int nt = t >> 2, tq = t & 3;
        int c0 = nt * 8 + tq * 2;
        g_w1w2[t] = make_float4(w1[128 * DIMD + c0], w1[128 * DIMD + c0 + 1],
                                w2[c0], w2[c0 + 1]);
    }
}

// ---------------- fused kernel ----------------
__global__ __launch_bounds__(256, 2) void fused_kernel(
    const float* __restrict__ self_v,   // [BN,128]
    const float* __restrict__ neigh,    // [BN,12,128]
    const float* __restrict__ nw,       // [BN,12]
    const float* __restrict__ extra,    // [BN,128]
    float* __restrict__ out)            // [BN,128]
{
    __shared__ uint32_t cat_h[8 * 132];   // fp16x2 cat rows, pad 132 (conflict-free)

    const int tid = threadIdx.x, wid = tid >> 5, lane = tid & 31;
    const int g = lane >> 2, tg = lane & 3;
    const int bn0 = blockIdx.x * 8;
    const int bn = bn0 + wid;

    // ---- Phase 1: gemm1 for this bn (rows = 12 neighbors, 4 pad)
    const bool hasR1 = (g < 4);
    const float* nr0 = neigh + (size_t)(bn * KK + g) * DIMD;
    const float* nr1 = neigh + (size_t)(bn * KK + (hasR1 ? g + 8 : g)) * DIMD;
    const float* er  = extra + (size_t)bn * DIMD;
    const float nw0 = __ldg(nw + bn * KK + g);
    const float nw1 = hasR1 ? __ldg(nw + bn * KK + g + 8) : 0.f;

    float acc[16][4];
#pragma unroll
    for (int nt = 0; nt < 16; nt++)
#pragma unroll
        for (int q = 0; q < 4; q++) acc[nt][q] = 0.f;

#pragma unroll 1
    for (int kt = 0; kt < 8; kt++) {
        const int c0 = kt * 16 + tg * 2;
        float2 e0 = *(const float2*)(er + c0);
        float2 e1 = *(const float2*)(er + c0 + 8);
        float2 n00 = *(const float2*)(nr0 + c0);
        float2 n01 = *(const float2*)(nr0 + c0 + 8);
        float2 n10 = *(const float2*)(nr1 + c0);
        float2 n11 = *(const float2*)(nr1 + c0 + 8);
        uint32_t a0 = packh(n00.x * e0.x, n00.y * e0.y);
        uint32_t a2 = packh(n01.x * e1.x, n01.y * e1.y);
        uint32_t a1 = hasR1 ? packh(n10.x * e0.x, n10.y * e0.y) : 0u;
        uint32_t a3 = hasR1 ? packh(n11.x * e1.x, n11.y * e1.y) : 0u;
#pragma unroll
        for (int nt = 0; nt < 16; nt++) {
            uint2 bq = __ldg(&g_bfrag1[(kt * 16 + nt) * 32 + lane]);
            mma16816h(acc[nt], a0, a1, a2, a3, bq.x, bq.y);
        }
    }

    // ---- scores: rowsum[j] = sum_n w2[n]*lrelu(D[row][n] + nw*w1last[n])
    float rowsum[2] = {0.f, 0.f};
#pragma unroll
    for (int nt = 0; nt < 16; nt++) {
        float4 ww = g_w1w2[nt * 4 + tg];
        float v0 = acc[nt][0] + nw0 * ww.x;
        float v1 = acc[nt][1] + nw0 * ww.y;
        float v2 = acc[nt][2] + nw1 * ww.x;
        float v3 = acc[nt][3] + nw1 * ww.y;
        v0 = fmaxf(v0, 0.f) + 0.2f * fminf(v0, 0.f);
        v1 = fmaxf(v1, 0.f) + 0.2f * fminf(v1, 0.f);
        v2 = fmaxf(v2, 0.f) + 0.2f * fminf(v2, 0.f);
        v3 = fmaxf(v3, 0.f) + 0.2f * fminf(v3, 0.f);
        rowsum[0] = fmaf(v0, ww.z, fmaf(v1, ww.w, rowsum[0]));
        rowsum[1] = fmaf(v2, ww.z, fmaf(v3, ww.w, rowsum[1]));
    }
#pragma unroll
    for (int j = 0; j < 2; j++) {
        rowsum[j] += __shfl_xor_sync(0xffffffffu, rowsum[j], 1);
        rowsum[j] += __shfl_xor_sync(0xffffffffu, rowsum[j], 2);
    }

    // ---- softmax over the 12 scores (all lanes, via shfl gather)
    float alpha[KK];
    {
        float s[KK];
#pragma unroll
        for (int k = 0; k < 8; k++)
            s[k] = __shfl_sync(0xffffffffu, rowsum[0], 4 * k);
#pragma unroll
        for (int k = 8; k < KK; k++)
            s[k] = __shfl_sync(0xffffffffu, rowsum[1], 4 * (k - 8));
        float mx = s[0];
#pragma unroll
        for (int k = 1; k < KK; k++) mx = fmaxf(mx, s[k]);
        float tot = 0.f;
#pragma unroll
        for (int k = 0; k < KK; k++) { alpha[k] = __expf(s[k] - mx); tot += alpha[k]; }
        float inv = 1.f / tot;
#pragma unroll
        for (int k = 0; k < KK; k++) alpha[k] *= inv;
    }

    // ---- agg (neigh reload = L1 hit) + pack cat to fp16 smem
    {
        const float4* nb4 = (const float4*)(neigh + (size_t)bn * KK * DIMD);
        float4 agg = make_float4(0.f, 0.f, 0.f, 0.f);
#pragma unroll
        for (int k = 0; k < KK; k++) {
            float4 v = nb4[k * 32 + lane];
            agg.x = fmaf(alpha[k], v.x, agg.x);
            agg.y = fmaf(alpha[k], v.y, agg.y);
            agg.z = fmaf(alpha[k], v.z, agg.z);
            agg.w = fmaf(alpha[k], v.w, agg.w);
        }
        float4 sv = *((const float4*)(self_v + (size_t)bn * DIMD) + lane);
        cat_h[wid * 132 + 2 * lane]          = packh(sv.x, sv.y);
        cat_h[wid * 132 + 2 * lane + 1]      = packh(sv.z, sv.w);
        cat_h[wid * 132 + 64 + 2 * lane]     = packh(agg.x, agg.y);
        cat_h[wid * 132 + 64 + 2 * lane + 1] = packh(agg.z, agg.w);
    }
    __syncthreads();

    // ---- Phase 3: w3 GEMM. m16 tile: rows 0..7 = the CTA's 8 bn (8..15 pad).
    // Warp handles nt = {2wid, 2wid+1}; 16 kt over K=256.
    float acc3[2][4];
#pragma unroll
    for (int t = 0; t < 2; t++)
#pragma unroll
        for (int q = 0; q < 4; q++) acc3[t][q] = 0.f;

#pragma unroll
    for (int kt = 0; kt < 16; kt++) {
        uint32_t a0 = cat_h[g * 132 + kt * 8 + tg];
        uint32_t a2 = cat_h[g * 132 + kt * 8 + tg + 4];
#pragma unroll
        for (int t = 0; t < 2; t++) {
            int nt = 2 * wid + t;
            uint2 bq = __ldg(&g_bfrag3[(kt * 16 + nt) * 32 + lane]);
            mma16816h(acc3[t], a0, 0u, a2, 0u, bq.x, bq.y);
        }
    }

    // ---- write out: D row g = bn0+g, cols nt*8 + 2tg, +1
    {
        const size_t ob = (size_t)(bn0 + g) * DIMD;
#pragma unroll
        for (int t = 0; t < 2; t++) {
            int nt = 2 * wid + t;
            float2 o = make_float2(fmaxf(acc3[t][0], 0.f), fmaxf(acc3[t][1], 0.f));
            *(float2*)(out + ob + nt * 8 + 2 * tg) = o;
        }
    }
}

// ---------------- launch ----------------
extern "C" void kernel_launch(void* const* d_in, const int* in_sizes, int n_in,
                              void* d_out, int out_size) {
    const float* self_v = (const float*)d_in[0];
    const float* neigh  = (const float*)d_in[1];
    const float* nw     = (const float*)d_in[2];
    const float* extra  = (const float*)d_in[3];
    const float* w1     = (const float*)d_in[6];
    const float* w2     = (const float*)d_in[7];
    const float* w3     = (const float*)d_in[8];
    float* out = (float*)d_out;

    prep_kernel<<<49, 256>>>(w1, w2, w3);
    fused_kernel<<<BN_TOTAL / 8, 256>>>(self_v, neigh, nw, extra, out);
}

// round 9
// speedup vs baseline: 6.1052x; 1.1402x over previous
#include <cuda_runtime.h>
#include <cuda_fp16.h>
#include <cstdint>

// GlobalAggregator fused v3: B=128,N=512,K=12,DIM=128.
// CTA = 192 thr (6 warps) = 16 bn = 192 feat rows = 12 m16 tiles = 2 tiles/warp.
// gemm1 (HMMA, smem feat via ldmatrix) -> scores -> softmax -> agg -> w3 HMMA.

#define KK 12
#define DIMD 128
#define BN_TOTAL (128 * 512)
#define TILE_BN 16
#define TILE_R 192
#define GRID_F (BN_TOTAL / TILE_BN)   // 4096
#define FSTR 68                        // feat row stride in u32 (136 fp16)
#define NWARP 6

__device__ uint2 g_bfrag1[128 * 32];   // w1 frags, [(nt*8+kt)*32+lane]
__device__ uint2 g_bfrag3[256 * 32];   // w3 frags, [(kt*16+nt)*32+lane]
__device__ float4 g_w1w2[64];          // (w1last pair, w2 pair) per (nt, tg)

// ---- helpers ----
__device__ __forceinline__ uint32_t packh(float lo, float hi) {
    uint32_t r;
    asm("cvt.rn.f16x2.f32 %0, %1, %2;" : "=r"(r) : "f"(hi), "f"(lo));
    return r;
}
__device__ __forceinline__ void mma16816h(float c[4],
                                          uint32_t a0, uint32_t a1, uint32_t a2, uint32_t a3,
                                          uint32_t b0, uint32_t b1) {
    asm volatile("mma.sync.aligned.m16n8k16.row.col.f32.f16.f16.f32 "
                 "{%0,%1,%2,%3},{%4,%5,%6,%7},{%8,%9},{%0,%1,%2,%3};"
                 : "+f"(c[0]), "+f"(c[1]), "+f"(c[2]), "+f"(c[3])
                 : "r"(a0), "r"(a1), "r"(a2), "r"(a3), "r"(b0), "r"(b1));
}
__device__ __forceinline__ void ldsm4(uint32_t r[4], uint32_t saddr) {
    asm volatile("ldmatrix.sync.aligned.m8n8.x4.shared.b16 {%0,%1,%2,%3}, [%4];"
                 : "=r"(r[0]), "=r"(r[1]), "=r"(r[2]), "=r"(r[3]) : "r"(saddr));
}
__device__ __forceinline__ uint32_t smem_u32(const void* p) {
    uint32_t a;
    asm("{ .reg .u64 t; cvta.to.shared.u64 t, %1; cvt.u32.u64 %0, t; }" : "=r"(a) : "l"(p));
    return a;
}
__device__ __forceinline__ float lrelu(float x) {
    return fmaxf(x, 0.f) + 0.2f * fminf(x, 0.f);
}

// ---------------- prep: bake B fragments ----------------
__global__ void prep_kernel(const float* __restrict__ w1,
                            const float* __restrict__ w2,
                            const float* __restrict__ w3) {
    int idx = blockIdx.x * 256 + threadIdx.x;
    if (idx < 4096) {                       // w1 frags, [nt][kt] order
        int gi = idx >> 5, lane = idx & 31;
        int nt = gi >> 3, kt = gi & 7;
        int g = lane >> 2, tg = lane & 3;
        int n = nt * 8 + g, k0 = kt * 16 + tg * 2;
        float v0 = w1[k0 * DIMD + n],       v1 = w1[(k0 + 1) * DIMD + n];
        float v2 = w1[(k0 + 8) * DIMD + n], v3 = w1[(k0 + 9) * DIMD + n];
        g_bfrag1[idx] = make_uint2(packh(v0, v1), packh(v2, v3));
    } else if (idx < 4096 + 8192) {         // w3 frags, [kt][nt] order (K=256)
        int j = idx - 4096;
        int gi = j >> 5, lane = j & 31;
        int kt = gi >> 4, nt = gi & 15;
        int g = lane >> 2, tg = lane & 3;
        int n = nt * 8 + g, k0 = kt * 16 + tg * 2;
        float v0 = w3[k0 * DIMD + n],       v1 = w3[(k0 + 1) * DIMD + n];
        float v2 = w3[(k0 + 8) * DIMD + n], v3 = w3[(k0 + 9) * DIMD + n];
        g_bfrag3[j] = make_uint2(packh(v0, v1), packh(v2, v3));
    } else if (idx < 4096 + 8192 + 64) {
        int t = idx - 4096 - 8192;
        int nt = t >> 2, tq = t & 3;
        int c0 = nt * 8 + tq * 2;
        g_w1w2[t] = make_float4(w1[128 * DIMD + c0], w1[128 * DIMD + c0 + 1],
                                w2[c0], w2[c0 + 1]);
    }
}

// ---------------- fused kernel ----------------
// dyn smem: feat 192*68 u32 | scores 192 f32 | cat 16*132 u32  -> 61440 B
#define SM_SCORES (TILE_R * FSTR)
#define SM_CAT    (TILE_R * FSTR + TILE_R)
#define SM_BYTES  ((TILE_R * FSTR + TILE_R + 16 * 132) * 4)

__global__ __launch_bounds__(192, 2) void fused_kernel(
    const float* __restrict__ self_v,   // [BN,128]
    const float* __restrict__ neigh,    // [BN,12,128]
    const float* __restrict__ nw,       // [BN,12]
    const float* __restrict__ extra,    // [BN,128]
    float* __restrict__ out)            // [BN,128]
{
    extern __shared__ uint32_t sm[];
    uint32_t* feat = sm;
    float* scores_s = (float*)(sm + SM_SCORES);
    uint32_t* cat_h = sm + SM_CAT;

    const int tid = threadIdx.x, wid = tid >> 5, lane = tid & 31;
    const int g = lane >> 2, tg = lane & 3;
    const int bn0 = blockIdx.x * TILE_BN;
    const size_t row0 = (size_t)blockIdx.x * TILE_R;

    // ---- stage feat = neigh * extra (fp16) into smem, CTA-cooperative
    {
        const float4* ng4 = (const float4*)neigh;
        const float4* ex4 = (const float4*)extra;
#pragma unroll
        for (int r = wid; r < TILE_R; r += NWARP) {
            size_t gr = row0 + r;
            int bnr = bn0 + r / KK;
            float4 nv = ng4[gr * 32 + lane];
            float4 ev = __ldg(ex4 + (size_t)bnr * 32 + lane);
            feat[r * FSTR + 2 * lane]     = packh(nv.x * ev.x, nv.y * ev.y);
            feat[r * FSTR + 2 * lane + 1] = packh(nv.z * ev.z, nv.w * ev.w);
        }
    }
    __syncthreads();

    // ---- gemm1: warp owns rows 32*wid..+31 (2 m16 tiles); 6*32 = 192 rows exactly
    uint32_t A[2][8][4];
    {
        const uint32_t fb = smem_u32(feat);
#pragma unroll
        for (int t = 0; t < 2; t++) {
            uint32_t ridx = (uint32_t)(32 * wid + 16 * t + (lane & 15));
#pragma unroll
            for (int kt = 0; kt < 8; kt++) {
                uint32_t idx = ridx * FSTR + kt * 8 + (lane >> 4) * 4;
                ldsm4(A[t][kt], fb + idx * 4);
            }
        }
    }

    float rs[2][2] = {{0.f, 0.f}, {0.f, 0.f}};
    float nwr[2][2];
#pragma unroll
    for (int t = 0; t < 2; t++) {
        size_t gr = row0 + 32 * wid + 16 * t + g;
        nwr[t][0] = __ldg(nw + gr);
        nwr[t][1] = __ldg(nw + gr + 8);
    }

#pragma unroll 1
    for (int nt = 0; nt < 16; nt++) {
        float p[4] = {0.f, 0.f, 0.f, 0.f};
        float q[4] = {0.f, 0.f, 0.f, 0.f};
#pragma unroll
        for (int kt = 0; kt < 8; kt++) {
            uint2 b = __ldg(&g_bfrag1[(nt * 8 + kt) * 32 + lane]);
            mma16816h(p, A[0][kt][0], A[0][kt][1], A[0][kt][2], A[0][kt][3], b.x, b.y);
            mma16816h(q, A[1][kt][0], A[1][kt][1], A[1][kt][2], A[1][kt][3], b.x, b.y);
        }
        float4 ww = g_w1w2[nt * 4 + tg];
        float v0 = lrelu(p[0] + nwr[0][0] * ww.x);
        float v1 = lrelu(p[1] + nwr[0][0] * ww.y);
        float v2 = lrelu(p[2] + nwr[0][1] * ww.x);
        float v3 = lrelu(p[3] + nwr[0][1] * ww.y);
        rs[0][0] = fmaf(v0, ww.z, fmaf(v1, ww.w, rs[0][0]));
        rs[0][1] = fmaf(v2, ww.z, fmaf(v3, ww.w, rs[0][1]));
        v0 = lrelu(q[0] + nwr[1][0] * ww.x);
        v1 = lrelu(q[1] + nwr[1][0] * ww.y);
        v2 = lrelu(q[2] + nwr[1][1] * ww.x);
        v3 = lrelu(q[3] + nwr[1][1] * ww.y);
        rs[1][0] = fmaf(v0, ww.z, fmaf(v1, ww.w, rs[1][0]));
        rs[1][1] = fmaf(v2, ww.z, fmaf(v3, ww.w, rs[1][1]));
    }
#pragma unroll
    for (int t = 0; t < 2; t++) {
#pragma unroll
        for (int j = 0; j < 2; j++) {
            rs[t][j] += __shfl_xor_sync(0xffffffffu, rs[t][j], 1);
            rs[t][j] += __shfl_xor_sync(0xffffffffu, rs[t][j], 2);
        }
        if (tg == 0) {
            scores_s[32 * wid + 16 * t + g] = rs[t][0];
            scores_s[32 * wid + 16 * t + g + 8] = rs[t][1];
        }
    }
    __syncthreads();

    // ---- softmax + agg + cat: 16 bn over 6 warps
    for (int bnl = wid; bnl < TILE_BN; bnl += NWARP) {
        const int gbn = bn0 + bnl;
        float alpha[KK];
        {
            float s[KK];
#pragma unroll
            for (int k = 0; k < KK; k++) s[k] = scores_s[bnl * KK + k];
            float mx = s[0];
#pragma unroll
            for (int k = 1; k < KK; k++) mx = fmaxf(mx, s[k]);
            float tot = 0.f;
#pragma unroll
            for (int k = 0; k < KK; k++) { alpha[k] = __expf(s[k] - mx); tot += alpha[k]; }
            float inv = 1.f / tot;
#pragma unroll
            for (int k = 0; k < KK; k++) alpha[k] *= inv;
        }
        const float4* nb4 = (const float4*)neigh + (size_t)gbn * KK * 32;
        float4 agg = make_float4(0.f, 0.f, 0.f, 0.f);
#pragma unroll
        for (int k = 0; k < KK; k++) {
            float4 v = nb4[k * 32 + lane];   // L1 hit (staged moments ago)
            agg.x = fmaf(alpha[k], v.x, agg.x);
            agg.y = fmaf(alpha[k], v.y, agg.y);
            agg.z = fmaf(alpha[k], v.z, agg.z);
            agg.w = fmaf(alpha[k], v.w, agg.w);
        }
        float4 sv = *((const float4*)self_v + (size_t)gbn * 32 + lane);
        cat_h[bnl * 132 + 2 * lane]          = packh(sv.x, sv.y);
        cat_h[bnl * 132 + 2 * lane + 1]      = packh(sv.z, sv.w);
        cat_h[bnl * 132 + 64 + 2 * lane]     = packh(agg.x, agg.y);
        cat_h[bnl * 132 + 64 + 2 * lane + 1] = packh(agg.z, agg.w);
    }
    __syncthreads();

    // ---- w3 GEMM: one full m16 tile (16 bn), 16 nt over 6 warps
    for (int nt = wid; nt < 16; nt += NWARP) {
        float acc3[4] = {0.f, 0.f, 0.f, 0.f};
#pragma unroll
        for (int kt = 0; kt < 16; kt++) {
            uint32_t a0 = cat_h[g * 132 + kt * 8 + tg];
            uint32_t a1 = cat_h[(g + 8) * 132 + kt * 8 + tg];
            uint32_t a2 = cat_h[g * 132 + kt * 8 + tg + 4];
            uint32_t a3 = cat_h[(g + 8) * 132 + kt * 8 + tg + 4];
            uint2 bq = __ldg(&g_bfrag3[(kt * 16 + nt) * 32 + lane]);
            mma16816h(acc3, a0, a1, a2, a3, bq.x, bq.y);
        }
        float2 o0 = make_float2(fmaxf(acc3[0], 0.f), fmaxf(acc3[1], 0.f));
        float2 o1 = make_float2(fmaxf(acc3[2], 0.f), fmaxf(acc3[3], 0.f));
        *(float2*)(out + (size_t)(bn0 + g) * DIMD + nt * 8 + 2 * tg) = o0;
        *(float2*)(out + (size_t)(bn0 + g + 8) * DIMD + nt * 8 + 2 * tg) = o1;
    }
}

// ---------------- launch ----------------
extern "C" void kernel_launch(void* const* d_in, const int* in_sizes, int n_in,
                              void* d_out, int out_size) {
    const float* self_v = (const float*)d_in[0];
    const float* neigh  = (const float*)d_in[1];
    const float* nw     = (const float*)d_in[2];
    const float* extra  = (const float*)d_in[3];
    const float* w1     = (const float*)d_in[6];
    const float* w2     = (const float*)d_in[7];
    const float* w3     = (const float*)d_in[8];
    float* out = (float*)d_out;

    static bool attr_set = false;
    if (!attr_set) {
        cudaFuncSetAttribute(fused_kernel, cudaFuncAttributeMaxDynamicSharedMemorySize, SM_BYTES);
        attr_set = true;
    }

    prep_kernel<<<49, 256>>>(w1, w2, w3);
    fused_kernel<<<GRID_F, 192, SM_BYTES>>>(self_v, neigh, nw, extra, out);
}

// round 10
// speedup vs baseline: 6.6707x; 1.0926x over previous
#include <cuda_runtime.h>
#include <cuda_fp16.h>
#include <cstdint>

// GlobalAggregator fused v4: B=128,N=512,K=12,DIM=128.
// CTA = 192 thr (6 warps) = 16 bn = 192 rows = 12 m16 tiles (2/warp, processed
// one at a time: A=32 regs). nt unrolled x4 -> 4 independent HMMA chains.

#define KK 12
#define DIMD 128
#define BN_TOTAL (128 * 512)
#define TILE_BN 16
#define TILE_R 192
#define GRID_F (BN_TOTAL / TILE_BN)   // 4096
#define FSTR 68                        // feat row stride in u32 (136 fp16)
#define NWARP 6

__device__ uint2 g_bfrag1[128 * 32];   // w1 frags, [(nt*8+kt)*32+lane]
__device__ uint2 g_bfrag3[256 * 32];   // w3 frags, [(kt*16+nt)*32+lane]
__device__ float4 g_w1w2[64];          // (w1last pair, w2 pair) per (nt, tg)

// ---- helpers ----
__device__ __forceinline__ uint32_t packh(float lo, float hi) {
    uint32_t r;
    asm("cvt.rn.f16x2.f32 %0, %1, %2;" : "=r"(r) : "f"(hi), "f"(lo));
    return r;
}
__device__ __forceinline__ void mma16816h(float c[4],
                                          uint32_t a0, uint32_t a1, uint32_t a2, uint32_t a3,
                                          uint32_t b0, uint32_t b1) {
    asm volatile("mma.sync.aligned.m16n8k16.row.col.f32.f16.f16.f32 "
                 "{%0,%1,%2,%3},{%4,%5,%6,%7},{%8,%9},{%0,%1,%2,%3};"
                 : "+f"(c[0]), "+f"(c[1]), "+f"(c[2]), "+f"(c[3])
                 : "r"(a0), "r"(a1), "r"(a2), "r"(a3), "r"(b0), "r"(b1));
}
__device__ __forceinline__ void ldsm4(uint32_t r[4], uint32_t saddr) {
    asm volatile("ldmatrix.sync.aligned.m8n8.x4.shared.b16 {%0,%1,%2,%3}, [%4];"
                 : "=r"(r[0]), "=r"(r[1]), "=r"(r[2]), "=r"(r[3]) : "r"(saddr));
}
__device__ __forceinline__ uint32_t smem_u32(const void* p) {
    uint32_t a;
    asm("{ .reg .u64 t; cvta.to.shared.u64 t, %1; cvt.u32.u64 %0, t; }" : "=r"(a) : "l"(p));
    return a;
}
__device__ __forceinline__ float lrelu(float x) {
    return fmaxf(x, 0.f) + 0.2f * fminf(x, 0.f);
}

// ---------------- prep: bake B fragments ----------------
__global__ void prep_kernel(const float* __restrict__ w1,
                            const float* __restrict__ w2,
                            const float* __restrict__ w3) {
    int idx = blockIdx.x * 256 + threadIdx.x;
    if (idx < 4096) {                       // w1 frags, [nt][kt] order
        int gi = idx >> 5, lane = idx & 31;
        int nt = gi >> 3, kt = gi & 7;
        int g = lane >> 2, tg = lane & 3;
        int n = nt * 8 + g, k0 = kt * 16 + tg * 2;
        float v0 = w1[k0 * DIMD + n],       v1 = w1[(k0 + 1) * DIMD + n];
        float v2 = w1[(k0 + 8) * DIMD + n], v3 = w1[(k0 + 9) * DIMD + n];
        g_bfrag1[idx] = make_uint2(packh(v0, v1), packh(v2, v3));
    } else if (idx < 4096 + 8192) {         // w3 frags, [kt][nt] order (K=256)
        int j = idx - 4096;
        int gi = j >> 5, lane = j & 31;
        int kt = gi >> 4, nt = gi & 15;
        int g = lane >> 2, tg = lane & 3;
        int n = nt * 8 + g, k0 = kt * 16 + tg * 2;
        float v0 = w3[k0 * DIMD + n],       v1 = w3[(k0 + 1) * DIMD + n];
        float v2 = w3[(k0 + 8) * DIMD + n], v3 = w3[(k0 + 9) * DIMD + n];
        g_bfrag3[j] = make_uint2(packh(v0, v1), packh(v2, v3));
    } else if (idx < 4096 + 8192 + 64) {
        int t = idx - 4096 - 8192;
        int nt = t >> 2, tq = t & 3;
        int c0 = nt * 8 + tq * 2;
        g_w1w2[t] = make_float4(w1[128 * DIMD + c0], w1[128 * DIMD + c0 + 1],
                                w2[c0], w2[c0 + 1]);
    }
}

// ---------------- fused kernel ----------------
// dyn smem: feat 192*68 u32 | scores 192 f32 | cat 16*132 u32  -> 61440 B
#define SM_SCORES (TILE_R * FSTR)
#define SM_CAT    (TILE_R * FSTR + TILE_R)
#define SM_BYTES  ((TILE_R * FSTR + TILE_R + 16 * 132) * 4)

__global__ __launch_bounds__(192, 3) void fused_kernel(
    const float* __restrict__ self_v,   // [BN,128]
    const float* __restrict__ neigh,    // [BN,12,128]
    const float* __restrict__ nw,       // [BN,12]
    const float* __restrict__ extra,    // [BN,128]
    float* __restrict__ out)            // [BN,128]
{
    extern __shared__ uint32_t sm[];
    uint32_t* feat = sm;
    float* scores_s = (float*)(sm + SM_SCORES);
    uint32_t* cat_h = sm + SM_CAT;

    const int tid = threadIdx.x, wid = tid >> 5, lane = tid & 31;
    const int g = lane >> 2, tg = lane & 3;
    const int bn0 = blockIdx.x * TILE_BN;
    const size_t row0 = (size_t)blockIdx.x * TILE_R;

    // ---- stage feat = neigh * extra (fp16) into smem, CTA-cooperative
    {
        const float4* ng4 = (const float4*)neigh;
        const float4* ex4 = (const float4*)extra;
#pragma unroll
        for (int r = wid; r < TILE_R; r += NWARP) {
            size_t gr = row0 + r;
            int bnr = bn0 + r / KK;
            float4 nv = ng4[gr * 32 + lane];
            float4 ev = __ldg(ex4 + (size_t)bnr * 32 + lane);
            feat[r * FSTR + 2 * lane]     = packh(nv.x * ev.x, nv.y * ev.y);
            feat[r * FSTR + 2 * lane + 1] = packh(nv.z * ev.z, nv.w * ev.w);
        }
    }
    __syncthreads();

    // ---- gemm1: warp owns 2 m16 tiles, processed one at a time (A = 32 regs)
    const uint32_t fb = smem_u32(feat);
#pragma unroll
    for (int t = 0; t < 2; t++) {
        uint32_t A[8][4];
        {
            uint32_t ridx = (uint32_t)(32 * wid + 16 * t + (lane & 15));
#pragma unroll
            for (int kt = 0; kt < 8; kt++) {
                uint32_t idx = ridx * FSTR + kt * 8 + (lane >> 4) * 4;
                ldsm4(A[kt], fb + idx * 4);
            }
        }
        const size_t gr = row0 + 32 * wid + 16 * t + g;
        const float nw0 = __ldg(nw + gr);
        const float nw1 = __ldg(nw + gr + 8);
        float rs0 = 0.f, rs1 = 0.f;

#pragma unroll
        for (int nt0 = 0; nt0 < 16; nt0 += 4) {
            float acc[4][4];
#pragma unroll
            for (int u = 0; u < 4; u++)
#pragma unroll
                for (int q = 0; q < 4; q++) acc[u][q] = 0.f;
#pragma unroll
            for (int kt = 0; kt < 8; kt++) {
#pragma unroll
                for (int u = 0; u < 4; u++) {
                    uint2 b = __ldg(&g_bfrag1[((nt0 + u) * 8 + kt) * 32 + lane]);
                    mma16816h(acc[u], A[kt][0], A[kt][1], A[kt][2], A[kt][3], b.x, b.y);
                }
            }
#pragma unroll
            for (int u = 0; u < 4; u++) {
                float4 ww = g_w1w2[(nt0 + u) * 4 + tg];
                float v0 = lrelu(acc[u][0] + nw0 * ww.x);
                float v1 = lrelu(acc[u][1] + nw0 * ww.y);
                float v2 = lrelu(acc[u][2] + nw1 * ww.x);
                float v3 = lrelu(acc[u][3] + nw1 * ww.y);
                rs0 = fmaf(v0, ww.z, fmaf(v1, ww.w, rs0));
                rs1 = fmaf(v2, ww.z, fmaf(v3, ww.w, rs1));
            }
        }
        rs0 += __shfl_xor_sync(0xffffffffu, rs0, 1);
        rs0 += __shfl_xor_sync(0xffffffffu, rs0, 2);
        rs1 += __shfl_xor_sync(0xffffffffu, rs1, 1);
        rs1 += __shfl_xor_sync(0xffffffffu, rs1, 2);
        if (tg == 0) {
            scores_s[32 * wid + 16 * t + g] = rs0;
            scores_s[32 * wid + 16 * t + g + 8] = rs1;
        }
    }
    __syncthreads();

    // ---- softmax + agg + cat: 16 bn over 6 warps
    for (int bnl = wid; bnl < TILE_BN; bnl += NWARP) {
        const int gbn = bn0 + bnl;
        float alpha[KK];
        {
            float s[KK];
#pragma unroll
            for (int k = 0; k < KK; k++) s[k] = scores_s[bnl * KK + k];
            float mx = s[0];
#pragma unroll
            for (int k = 1; k < KK; k++) mx = fmaxf(mx, s[k]);
            float tot = 0.f;
#pragma unroll
            for (int k = 0; k < KK; k++) { alpha[k] = __expf(s[k] - mx); tot += alpha[k]; }
            float inv = 1.f / tot;
#pragma unroll
            for (int k = 0; k < KK; k++) alpha[k] *= inv;
        }
        const float4* nb4 = (const float4*)neigh + (size_t)gbn * KK * 32;
        float4 agg = make_float4(0.f, 0.f, 0.f, 0.f);
#pragma unroll
        for (int k = 0; k < KK; k++) {
            float4 v = nb4[k * 32 + lane];   // L1 hit (staged moments ago)
            agg.x = fmaf(alpha[k], v.x, agg.x);
            agg.y = fmaf(alpha[k], v.y, agg.y);
            agg.z = fmaf(alpha[k], v.z, agg.z);
            agg.w = fmaf(alpha[k], v.w, agg.w);
        }
        float4 sv = *((const float4*)self_v + (size_t)gbn * 32 + lane);
        cat_h[bnl * 132 + 2 * lane]          = packh(sv.x, sv.y);
        cat_h[bnl * 132 + 2 * lane + 1]      = packh(sv.z, sv.w);
        cat_h[bnl * 132 + 64 + 2 * lane]     = packh(agg.x, agg.y);
        cat_h[bnl * 132 + 64 + 2 * lane + 1] = packh(agg.z, agg.w);
    }
    __syncthreads();

    // ---- w3 GEMM: one full m16 tile (16 bn), 16 nt over 6 warps
    for (int nt = wid; nt < 16; nt += NWARP) {
        float acc3[4] = {0.f, 0.f, 0.f, 0.f};
#pragma unroll
        for (int kt = 0; kt < 16; kt++) {
            uint32_t a0 = cat_h[g * 132 + kt * 8 + tg];
            uint32_t a1 = cat_h[(g + 8) * 132 + kt * 8 + tg];
            uint32_t a2 = cat_h[g * 132 + kt * 8 + tg + 4];
            uint32_t a3 = cat_h[(g + 8) * 132 + kt * 8 + tg + 4];
            uint2 bq = __ldg(&g_bfrag3[(kt * 16 + nt) * 32 + lane]);
            mma16816h(acc3, a0, a1, a2, a3, bq.x, bq.y);
        }
        float2 o0 = make_float2(fmaxf(acc3[0], 0.f), fmaxf(acc3[1], 0.f));
        float2 o1 = make_float2(fmaxf(acc3[2], 0.f), fmaxf(acc3[3], 0.f));
        *(float2*)(out + (size_t)(bn0 + g) * DIMD + nt * 8 + 2 * tg) = o0;
        *(float2*)(out + (size_t)(bn0 + g + 8) * DIMD + nt * 8 + 2 * tg) = o1;
    }
}

// ---------------- launch ----------------
extern "C" void kernel_launch(void* const* d_in, const int* in_sizes, int n_in,
                              void* d_out, int out_size) {
    const float* self_v = (const float*)d_in[0];
    const float* neigh  = (const float*)d_in[1];
    const float* nw     = (const float*)d_in[2];
    const float* extra  = (const float*)d_in[3];
    const float* w1     = (const float*)d_in[6];
    const float* w2     = (const float*)d_in[7];
    const float* w3     = (const float*)d_in[8];
    float* out = (float*)d_out;

    static bool attr_set = false;
    if (!attr_set) {
        cudaFuncSetAttribute(fused_kernel, cudaFuncAttributeMaxDynamicSharedMemorySize, SM_BYTES);
        attr_set = true;
    }

    prep_kernel<<<49, 256>>>(w1, w2, w3);
    fused_kernel<<<GRID_F, 192, SM_BYTES>>>(self_v, neigh, nw, extra, out);
}